// round 1
// baseline (speedup 1.0000x reference)
#include <cuda_runtime.h>
#include <cuda_bf16.h>
#include <cstdint>

// Problem constants (fixed by reference_code)
#define NN   100000
#define EE   3200000
#define FIN  512
#define HID  64
#define NC   16

// ---------------- scratch (static device globals; no allocation) -------------
__device__ float g_deg[NN];
__device__ float g_dinv[NN];
__device__ float g_norm[EE];
__device__ float g_h1[(size_t)NN * HID];   // x @ W1^T
__device__ float g_a1[(size_t)NN * HID];   // aggregated layer-1 (pre-relu)
__device__ float g_h2[(size_t)NN * NC];    // relu(a1) @ W2^T

// ---------------- helpers ----------------------------------------------------
__device__ __forceinline__ void red_add_f32x4(float4* addr, float4 v) {
    asm volatile("red.global.add.v4.f32 [%0], {%1, %2, %3, %4};"
                 :: "l"(addr), "f"(v.x), "f"(v.y), "f"(v.z), "f"(v.w)
                 : "memory");
}

// ---------------- degree / normalization -------------------------------------
__global__ void k_deg_init() {
    int i = blockIdx.x * blockDim.x + threadIdx.x;
    if (i < NN) g_deg[i] = 1.0f;            // self loop weight 1.0
}

__global__ void k_deg_acc(const int* __restrict__ col, const float* __restrict__ ew) {
    int e = blockIdx.x * blockDim.x + threadIdx.x;
    if (e < EE) atomicAdd(&g_deg[col[e]], ew[e]);
}

__global__ void k_dinv() {
    int i = blockIdx.x * blockDim.x + threadIdx.x;
    if (i < NN) g_dinv[i] = rsqrtf(g_deg[i]);   // deg >= 1 always
}

__global__ void k_norm(const int* __restrict__ row, const int* __restrict__ col,
                       const float* __restrict__ ew) {
    int e = blockIdx.x * blockDim.x + threadIdx.x;
    if (e < EE) g_norm[e] = g_dinv[row[e]] * ew[e] * g_dinv[col[e]];
}

// ---------------- GEMM1: h1[N,64] = x[N,512] @ W1[64,512]^T ------------------
// 64x64 tile per block, 256 threads, 4x4 register blocking, K-chunks of 16.
__global__ void k_gemm1(const float* __restrict__ x, const float* __restrict__ W1) {
    __shared__ __align__(16) float sA[16 * 68];   // sA[kk][i], padded stride 68
    __shared__ __align__(16) float sB[16 * 68];   // sB[kk][j]

    const int t  = threadIdx.x;
    const int ty = t >> 4;          // 0..15 -> row group
    const int tx = t & 15;          // 0..15 -> col group
    const int nb = blockIdx.x * 64;

    const int li = t >> 2;          // 0..63 (tile row for loads)
    const int lk = (t & 3) * 4;     // 0,4,8,12

    float acc[4][4];
    #pragma unroll
    for (int i = 0; i < 4; i++)
        #pragma unroll
        for (int j = 0; j < 4; j++) acc[i][j] = 0.0f;

    for (int k0 = 0; k0 < FIN; k0 += 16) {
        // stage A tile (transposed into k-major)
        float4 va = make_float4(0.f, 0.f, 0.f, 0.f);
        int r = nb + li;
        if (r < NN)
            va = *(const float4*)(x + (size_t)r * FIN + k0 + lk);
        sA[(lk + 0) * 68 + li] = va.x;
        sA[(lk + 1) * 68 + li] = va.y;
        sA[(lk + 2) * 68 + li] = va.z;
        sA[(lk + 3) * 68 + li] = va.w;

        // stage B tile (W1 row li = output channel li)
        float4 vb = *(const float4*)(W1 + (size_t)li * FIN + k0 + lk);
        sB[(lk + 0) * 68 + li] = vb.x;
        sB[(lk + 1) * 68 + li] = vb.y;
        sB[(lk + 2) * 68 + li] = vb.z;
        sB[(lk + 3) * 68 + li] = vb.w;

        __syncthreads();

        #pragma unroll
        for (int kk = 0; kk < 16; kk++) {
            float4 a = *(const float4*)&sA[kk * 68 + ty * 4];
            float4 b = *(const float4*)&sB[kk * 68 + tx * 4];
            acc[0][0] += a.x * b.x;  acc[0][1] += a.x * b.y;
            acc[0][2] += a.x * b.z;  acc[0][3] += a.x * b.w;
            acc[1][0] += a.y * b.x;  acc[1][1] += a.y * b.y;
            acc[1][2] += a.y * b.z;  acc[1][3] += a.y * b.w;
            acc[2][0] += a.z * b.x;  acc[2][1] += a.z * b.y;
            acc[2][2] += a.z * b.z;  acc[2][3] += a.z * b.w;
            acc[3][0] += a.w * b.x;  acc[3][1] += a.w * b.y;
            acc[3][2] += a.w * b.z;  acc[3][3] += a.w * b.w;
        }
        __syncthreads();
    }

    #pragma unroll
    for (int i = 0; i < 4; i++) {
        int r = nb + ty * 4 + i;
        if (r < NN) {
            float4 v = make_float4(acc[i][0], acc[i][1], acc[i][2], acc[i][3]);
            *(float4*)(g_h1 + (size_t)r * HID + tx * 4) = v;
        }
    }
}

// ---------------- layer-1 self-loop init + bias ------------------------------
// a1[n][:] = b1 + h1[n][:] * dinv[n]^2       (handles the self-loop edge)
__global__ void k_selfinit1(const float* __restrict__ b1) {
    int t = blockIdx.x * blockDim.x + threadIdx.x;   // N*16 float4 slots
    if (t >= NN * (HID / 4)) return;
    int n = t >> 4, j = t & 15;
    float s = g_dinv[n]; s *= s;
    const float4* h1_4 = (const float4*)g_h1;
    const float4* b1_4 = (const float4*)b1;
    float4 h = h1_4[t], bb = b1_4[j];
    float4 o = make_float4(bb.x + h.x * s, bb.y + h.y * s,
                           bb.z + h.z * s, bb.w + h.w * s);
    ((float4*)g_a1)[t] = o;
}

// ---------------- layer-1 edge scatter ---------------------------------------
__global__ void k_scatter1(const int* __restrict__ row, const int* __restrict__ col) {
    long long t = (long long)blockIdx.x * blockDim.x + threadIdx.x; // E*16 lanes
    if (t >= (long long)EE * (HID / 4)) return;
    int e = (int)(t >> 4), j = (int)(t & 15);
    int r = __ldg(&row[e]), c = __ldg(&col[e]);
    float w = __ldg(&g_norm[e]);
    float4 h = ((const float4*)g_h1)[(size_t)r * 16 + j];
    float4 v = make_float4(h.x * w, h.y * w, h.z * w, h.w * w);
    red_add_f32x4(((float4*)g_a1) + (size_t)c * 16 + j, v);
}

// ---------------- GEMM2: h2[N,16] = relu(a1)[N,64] @ W2[16,64]^T -------------
// 16 rows x 16 cols per block (256 threads, 1 output each).
__global__ void k_gemm2(const float* __restrict__ W2) {
    __shared__ float sX[16 * 65];    // relu(a1) tile, padded
    __shared__ float sW[16 * 65];    // W2, padded

    const int t  = threadIdx.x;
    const int nb = blockIdx.x * 16;
    const int r  = t >> 4;           // 0..15 row
    const int c  = t & 15;           // 0..15 class

    {   // stage tiles (4 floats per thread each)
        int idx = t * 4;
        int lr = idx >> 6, lk = idx & 63;
        float4 v = make_float4(0.f, 0.f, 0.f, 0.f);
        if (nb + lr < NN)
            v = *(const float4*)(g_a1 + (size_t)(nb + lr) * HID + lk);
        sX[lr * 65 + lk + 0] = fmaxf(v.x, 0.f);
        sX[lr * 65 + lk + 1] = fmaxf(v.y, 0.f);
        sX[lr * 65 + lk + 2] = fmaxf(v.z, 0.f);
        sX[lr * 65 + lk + 3] = fmaxf(v.w, 0.f);

        float4 w = *(const float4*)(W2 + (size_t)lr * HID + lk);
        sW[lr * 65 + lk + 0] = w.x;
        sW[lr * 65 + lk + 1] = w.y;
        sW[lr * 65 + lk + 2] = w.z;
        sW[lr * 65 + lk + 3] = w.w;
    }
    __syncthreads();

    float acc = 0.0f;
    #pragma unroll
    for (int k = 0; k < HID; k++)
        acc += sX[r * 65 + k] * sW[c * 65 + k];

    int n = nb + r;
    if (n < NN) g_h2[(size_t)n * NC + c] = acc;
}

// ---------------- layer-2 self-loop init + bias (writes d_out) --------------
__global__ void k_selfinit2(const float* __restrict__ b2, float* __restrict__ out) {
    int t = blockIdx.x * blockDim.x + threadIdx.x;   // N*4 float4 slots
    if (t >= NN * (NC / 4)) return;
    int n = t >> 2, j = t & 3;
    float s = g_dinv[n]; s *= s;
    float4 h = ((const float4*)g_h2)[t];
    float4 bb = ((const float4*)b2)[j];
    float4 o = make_float4(bb.x + h.x * s, bb.y + h.y * s,
                           bb.z + h.z * s, bb.w + h.w * s);
    ((float4*)out)[t] = o;
}

// ---------------- layer-2 edge scatter ---------------------------------------
__global__ void k_scatter2(const int* __restrict__ row, const int* __restrict__ col,
                           float* __restrict__ out) {
    long long t = (long long)blockIdx.x * blockDim.x + threadIdx.x; // E*4 lanes
    if (t >= (long long)EE * (NC / 4)) return;
    int e = (int)(t >> 2), j = (int)(t & 3);
    int r = __ldg(&row[e]), c = __ldg(&col[e]);
    float w = __ldg(&g_norm[e]);
    float4 h = ((const float4*)g_h2)[(size_t)r * 4 + j];
    float4 v = make_float4(h.x * w, h.y * w, h.z * w, h.w * w);
    red_add_f32x4(((float4*)out) + (size_t)c * 4 + j, v);
}

// ---------------- log_softmax over 16 classes, in-place on d_out -------------
__global__ void k_logsoftmax(float* __restrict__ out) {
    int n = blockIdx.x * blockDim.x + threadIdx.x;
    if (n >= NN) return;
    float4* o4 = (float4*)(out + (size_t)n * NC);
    float4 v0 = o4[0], v1 = o4[1], v2 = o4[2], v3 = o4[3];
    float vv[16] = {v0.x, v0.y, v0.z, v0.w, v1.x, v1.y, v1.z, v1.w,
                    v2.x, v2.y, v2.z, v2.w, v3.x, v3.y, v3.z, v3.w};
    float m = vv[0];
    #pragma unroll
    for (int i = 1; i < 16; i++) m = fmaxf(m, vv[i]);
    float s = 0.0f;
    #pragma unroll
    for (int i = 0; i < 16; i++) s += expf(vv[i] - m);
    float shift = m + logf(s);
    #pragma unroll
    for (int i = 0; i < 16; i++) vv[i] -= shift;
    o4[0] = make_float4(vv[0], vv[1], vv[2], vv[3]);
    o4[1] = make_float4(vv[4], vv[5], vv[6], vv[7]);
    o4[2] = make_float4(vv[8], vv[9], vv[10], vv[11]);
    o4[3] = make_float4(vv[12], vv[13], vv[14], vv[15]);
}

// ---------------- launch -----------------------------------------------------
extern "C" void kernel_launch(void* const* d_in, const int* in_sizes, int n_in,
                              void* d_out, int out_size) {
    const float* x   = (const float*)d_in[0];
    const int*   ei  = (const int*)  d_in[1];   // [2,E]: row then col
    const float* ew  = (const float*)d_in[2];
    const float* W1  = (const float*)d_in[3];
    const float* b1  = (const float*)d_in[4];
    const float* W2  = (const float*)d_in[5];
    const float* b2  = (const float*)d_in[6];
    float* out = (float*)d_out;

    const int* row = ei;
    const int* col = ei + EE;

    const int T = 256;

    k_deg_init<<<(NN + T - 1) / T, T>>>();
    k_deg_acc <<<(EE + T - 1) / T, T>>>(col, ew);
    k_dinv    <<<(NN + T - 1) / T, T>>>();
    k_norm    <<<(EE + T - 1) / T, T>>>(row, col, ew);

    k_gemm1<<<(NN + 63) / 64, T>>>(x, W1);

    k_selfinit1<<<(NN * (HID / 4) + T - 1) / T, T>>>(b1);
    {
        long long lanes = (long long)EE * (HID / 4);
        k_scatter1<<<(unsigned)((lanes + T - 1) / T), T>>>(row, col);
    }

    k_gemm2<<<(NN + 15) / 16, T>>>(W2);

    k_selfinit2<<<(NN * (NC / 4) + T - 1) / T, T>>>(b2, out);
    {
        long long lanes = (long long)EE * (NC / 4);
        k_scatter2<<<(unsigned)((lanes + T - 1) / T), T>>>(row, col, out);
    }

    k_logsoftmax<<<(NN + T - 1) / T, T>>>(out);
}

// round 3
// speedup vs baseline: 1.1311x; 1.1311x over previous
#include <cuda_runtime.h>
#include <cuda_bf16.h>
#include <cstdint>

// Problem constants (fixed by reference_code)
#define NN   100000
#define EE   3200000
#define FIN  512
#define HID  64
#define NC   16
#define NB1  ((NN + 1023) / 1024)   // 98 scan blocks

// ---------------- scratch (static device globals; no allocation) -------------
__device__ float g_deg[NN];
__device__ float g_dinv[NN];
__device__ int   g_cnt[NN];
__device__ int   g_off[NN];
__device__ int   g_cur[NN];
__device__ int   g_bsum[NB1];
__device__ int2  g_edge[EE];               // per-edge (src, norm-bits), CSR by col
__device__ float g_h1[(size_t)NN * HID];   // x @ W1^T
__device__ float g_a1[(size_t)NN * HID];   // relu(aggregated layer-1)
__device__ float g_h2[(size_t)NN * NC];    // a1 @ W2^T

// ---------------- init -------------------------------------------------------
__global__ void k_init() {
    int i = blockIdx.x * blockDim.x + threadIdx.x;
    if (i < NN) { g_deg[i] = 1.0f; g_cnt[i] = 0; g_cur[i] = 0; }
}

// ---------------- histogram: degree + in-edge counts -------------------------
__global__ void k_hist(const int* __restrict__ col, const float* __restrict__ ew) {
    int e = blockIdx.x * blockDim.x + threadIdx.x;
    if (e < EE) {
        int c = col[e];
        atomicAdd(&g_deg[c], ew[e]);
        atomicAdd(&g_cnt[c], 1);
    }
}

__global__ void k_dinv() {
    int i = blockIdx.x * blockDim.x + threadIdx.x;
    if (i < NN) g_dinv[i] = rsqrtf(g_deg[i]);   // deg >= 1 always (self loop)
}

// ---------------- 3-phase exclusive prefix scan of g_cnt ---------------------
__global__ void k_scan_block() {
    __shared__ int s[1024];
    int tid = threadIdx.x;
    int i = blockIdx.x * 1024 + tid;
    int v = (i < NN) ? g_cnt[i] : 0;
    s[tid] = v;
    __syncthreads();
    #pragma unroll
    for (int d = 1; d < 1024; d <<= 1) {
        int t = (tid >= d) ? s[tid - d] : 0;
        __syncthreads();
        s[tid] += t;
        __syncthreads();
    }
    if (i < NN) g_off[i] = s[tid] - v;           // exclusive within block
    if (tid == 1023) g_bsum[blockIdx.x] = s[1023];
}

__global__ void k_scan_sums() {
    __shared__ int s[128];
    int tid = threadIdx.x;
    int v = (tid < NB1) ? g_bsum[tid] : 0;
    s[tid] = v;
    __syncthreads();
    #pragma unroll
    for (int d = 1; d < 128; d <<= 1) {
        int t = (tid >= d) ? s[tid - d] : 0;
        __syncthreads();
        s[tid] += t;
        __syncthreads();
    }
    if (tid < NB1) g_bsum[tid] = s[tid] - v;     // exclusive block offsets
}

__global__ void k_scan_add() {
    int i = blockIdx.x * blockDim.x + threadIdx.x;
    if (i < NN) g_off[i] += g_bsum[i >> 10];
}

// ---------------- CSR placement (fuses norm computation) ---------------------
__global__ void k_place(const int* __restrict__ row, const int* __restrict__ col,
                        const float* __restrict__ ew) {
    int e = blockIdx.x * blockDim.x + threadIdx.x;
    if (e >= EE) return;
    int r = row[e], c = col[e];
    float w = g_dinv[r] * ew[e] * g_dinv[c];
    int pos = g_off[c] + atomicAdd(&g_cur[c], 1);
    g_edge[pos] = make_int2(r, __float_as_int(w));
}

// ---------------- GEMM1: h1[N,64] = x[N,512] @ W1[64,512]^T ------------------
__global__ void k_gemm1(const float* __restrict__ x, const float* __restrict__ W1) {
    __shared__ __align__(16) float sA[16 * 68];
    __shared__ __align__(16) float sB[16 * 68];

    const int t  = threadIdx.x;
    const int ty = t >> 4;
    const int tx = t & 15;
    const int nb = blockIdx.x * 64;

    const int li = t >> 2;
    const int lk = (t & 3) * 4;

    float acc[4][4];
    #pragma unroll
    for (int i = 0; i < 4; i++)
        #pragma unroll
        for (int j = 0; j < 4; j++) acc[i][j] = 0.0f;

    for (int k0 = 0; k0 < FIN; k0 += 16) {
        float4 va = make_float4(0.f, 0.f, 0.f, 0.f);
        int r = nb + li;
        if (r < NN)
            va = *(const float4*)(x + (size_t)r * FIN + k0 + lk);
        sA[(lk + 0) * 68 + li] = va.x;
        sA[(lk + 1) * 68 + li] = va.y;
        sA[(lk + 2) * 68 + li] = va.z;
        sA[(lk + 3) * 68 + li] = va.w;

        float4 vb = *(const float4*)(W1 + (size_t)li * FIN + k0 + lk);
        sB[(lk + 0) * 68 + li] = vb.x;
        sB[(lk + 1) * 68 + li] = vb.y;
        sB[(lk + 2) * 68 + li] = vb.z;
        sB[(lk + 3) * 68 + li] = vb.w;

        __syncthreads();

        #pragma unroll
        for (int kk = 0; kk < 16; kk++) {
            float4 a = *(const float4*)&sA[kk * 68 + ty * 4];
            float4 b = *(const float4*)&sB[kk * 68 + tx * 4];
            acc[0][0] += a.x * b.x;  acc[0][1] += a.x * b.y;
            acc[0][2] += a.x * b.z;  acc[0][3] += a.x * b.w;
            acc[1][0] += a.y * b.x;  acc[1][1] += a.y * b.y;
            acc[1][2] += a.y * b.z;  acc[1][3] += a.y * b.w;
            acc[2][0] += a.z * b.x;  acc[2][1] += a.z * b.y;
            acc[2][2] += a.z * b.z;  acc[2][3] += a.z * b.w;
            acc[3][0] += a.w * b.x;  acc[3][1] += a.w * b.y;
            acc[3][2] += a.w * b.z;  acc[3][3] += a.w * b.w;
        }
        __syncthreads();
    }

    #pragma unroll
    for (int i = 0; i < 4; i++) {
        int r = nb + ty * 4 + i;
        if (r < NN) {
            float4 v = make_float4(acc[i][0], acc[i][1], acc[i][2], acc[i][3]);
            *(float4*)(g_h1 + (size_t)r * HID + tx * 4) = v;
        }
    }
}

// ---------------- layer-1 aggregation: warp per node, CSR gather -------------
// a1[n] = relu(b1 + h1[n]*dinv[n]^2 + sum_e h1[src_e]*w_e)
__global__ void k_agg1(const float* __restrict__ b1) {
    int warp = (blockIdx.x * blockDim.x + threadIdx.x) >> 5;
    if (warp >= NN) return;
    int lane = threadIdx.x & 31;
    int half = lane >> 4;          // 2 edges in flight
    int fl   = lane & 15;          // feature group: floats fl*4..fl*4+3

    int start = g_off[warp];
    int end   = start + g_cnt[warp];

    const float4* h1 = (const float4*)g_h1;
    float4 acc = make_float4(0.f, 0.f, 0.f, 0.f);

    for (int e = start + half; e < end; e += 2) {
        int2 ed = __ldg(&g_edge[e]);
        float w = __int_as_float(ed.y);
        float4 h = h1[(size_t)ed.x * 16 + fl];
        acc.x = fmaf(h.x, w, acc.x);
        acc.y = fmaf(h.y, w, acc.y);
        acc.z = fmaf(h.z, w, acc.z);
        acc.w = fmaf(h.w, w, acc.w);
    }
    // combine the two halves
    acc.x += __shfl_xor_sync(0xffffffffu, acc.x, 16);
    acc.y += __shfl_xor_sync(0xffffffffu, acc.y, 16);
    acc.z += __shfl_xor_sync(0xffffffffu, acc.z, 16);
    acc.w += __shfl_xor_sync(0xffffffffu, acc.w, 16);

    float s = g_dinv[warp]; s *= s;
    float4 hs = h1[(size_t)warp * 16 + fl];
    float4 bb = ((const float4*)b1)[fl];
    float4 o;
    o.x = fmaxf(bb.x + acc.x + hs.x * s, 0.f);
    o.y = fmaxf(bb.y + acc.y + hs.y * s, 0.f);
    o.z = fmaxf(bb.z + acc.z + hs.z * s, 0.f);
    o.w = fmaxf(bb.w + acc.w + hs.w * s, 0.f);
    if (half == 0)
        ((float4*)g_a1)[(size_t)warp * 16 + fl] = o;
}

// ---------------- GEMM2: h2[N,16] = a1[N,64] @ W2[16,64]^T -------------------
__global__ void k_gemm2(const float* __restrict__ W2) {
    __shared__ float sX[16 * 65];
    __shared__ float sW[16 * 65];

    const int t  = threadIdx.x;
    const int nb = blockIdx.x * 16;
    const int r  = t >> 4;
    const int c  = t & 15;

    {
        int idx = t * 4;
        int lr = idx >> 6, lk = idx & 63;
        float4 v = make_float4(0.f, 0.f, 0.f, 0.f);
        if (nb + lr < NN)
            v = *(const float4*)(g_a1 + (size_t)(nb + lr) * HID + lk);
        sX[lr * 65 + lk + 0] = v.x;
        sX[lr * 65 + lk + 1] = v.y;
        sX[lr * 65 + lk + 2] = v.z;
        sX[lr * 65 + lk + 3] = v.w;

        float4 w = *(const float4*)(W2 + (size_t)lr * HID + lk);
        sW[lr * 65 + lk + 0] = w.x;
        sW[lr * 65 + lk + 1] = w.y;
        sW[lr * 65 + lk + 2] = w.z;
        sW[lr * 65 + lk + 3] = w.w;
    }
    __syncthreads();

    float acc = 0.0f;
    #pragma unroll
    for (int k = 0; k < HID; k++)
        acc += sX[r * 65 + k] * sW[c * 65 + k];

    int n = nb + r;
    if (n < NN) g_h2[(size_t)n * NC + c] = acc;
}

// ---------------- layer-2 aggregation + bias + log_softmax (fused) -----------
// warp per node: 8 edges in flight x 4 feature-groups (16 classes)
__global__ void k_agg2(const float* __restrict__ b2, float* __restrict__ out) {
    int warp = (blockIdx.x * blockDim.x + threadIdx.x) >> 5;
    if (warp >= NN) return;
    int lane = threadIdx.x & 31;
    int eg = lane >> 2;            // 0..7 edge group
    int fl = lane & 3;             // feature group: classes fl*4..fl*4+3

    int start = g_off[warp];
    int end   = start + g_cnt[warp];

    const float4* h2 = (const float4*)g_h2;
    float4 acc = make_float4(0.f, 0.f, 0.f, 0.f);

    for (int e = start + eg; e < end; e += 8) {
        int2 ed = __ldg(&g_edge[e]);
        float w = __int_as_float(ed.y);
        float4 h = h2[(size_t)ed.x * 4 + fl];
        acc.x = fmaf(h.x, w, acc.x);
        acc.y = fmaf(h.y, w, acc.y);
        acc.z = fmaf(h.z, w, acc.z);
        acc.w = fmaf(h.w, w, acc.w);
    }
    // reduce across the 8 edge groups (lanes differing by 4, 8, 16)
    #pragma unroll
    for (int d = 16; d >= 4; d >>= 1) {
        acc.x += __shfl_xor_sync(0xffffffffu, acc.x, d);
        acc.y += __shfl_xor_sync(0xffffffffu, acc.y, d);
        acc.z += __shfl_xor_sync(0xffffffffu, acc.z, d);
        acc.w += __shfl_xor_sync(0xffffffffu, acc.w, d);
    }

    float s = g_dinv[warp]; s *= s;
    float4 hs = h2[(size_t)warp * 4 + fl];
    float4 bb = ((const float4*)b2)[fl];
    float4 v;
    v.x = bb.x + acc.x + hs.x * s;
    v.y = bb.y + acc.y + hs.y * s;
    v.z = bb.z + acc.z + hs.z * s;
    v.w = bb.w + acc.w + hs.w * s;

    // log-softmax across 16 classes spread over 4 fl-lanes
    float m = fmaxf(fmaxf(v.x, v.y), fmaxf(v.z, v.w));
    m = fmaxf(m, __shfl_xor_sync(0xffffffffu, m, 1));
    m = fmaxf(m, __shfl_xor_sync(0xffffffffu, m, 2));
    float se = expf(v.x - m) + expf(v.y - m) + expf(v.z - m) + expf(v.w - m);
    se += __shfl_xor_sync(0xffffffffu, se, 1);
    se += __shfl_xor_sync(0xffffffffu, se, 2);
    float shift = m + logf(se);
    v.x -= shift; v.y -= shift; v.z -= shift; v.w -= shift;

    if (lane < 4)
        ((float4*)out)[(size_t)warp * 4 + fl] = v;
}

// ---------------- launch -----------------------------------------------------
extern "C" void kernel_launch(void* const* d_in, const int* in_sizes, int n_in,
                              void* d_out, int out_size) {
    const float* x   = (const float*)d_in[0];
    const int*   ei  = (const int*)  d_in[1];   // [2,E]: row then col
    const float* ew  = (const float*)d_in[2];
    const float* W1  = (const float*)d_in[3];
    const float* b1  = (const float*)d_in[4];
    const float* W2  = (const float*)d_in[5];
    const float* b2  = (const float*)d_in[6];
    float* out = (float*)d_out;

    const int* row = ei;
    const int* col = ei + EE;

    const int T = 256;

    k_init<<<(NN + T - 1) / T, T>>>();
    k_hist<<<(EE + T - 1) / T, T>>>(col, ew);
    k_dinv<<<(NN + T - 1) / T, T>>>();
    k_scan_block<<<NB1, 1024>>>();
    k_scan_sums<<<1, 128>>>();
    k_scan_add<<<(NN + T - 1) / T, T>>>();
    k_place<<<(EE + T - 1) / T, T>>>(row, col, ew);

    k_gemm1<<<(NN + 63) / 64, T>>>(x, W1);

    k_agg1<<<(NN * 32 + T - 1) / T, T>>>(b1);       // warp per node

    k_gemm2<<<(NN + 15) / 16, T>>>(W2);

    k_agg2<<<(NN * 32 + T - 1) / T, T>>>(b2, out);  // warp per node
}